// round 1
// baseline (speedup 1.0000x reference)
#include <cuda_runtime.h>
#include <math.h>

#define NQ    16
#define DIM   65536
#define BATCH 64
#define NCLS  23

// ---------------- scratch (static device allocations only) ----------------
__device__ float2 g_state[BATCH * DIM];      // 32 MB state
__device__ float2 g_U[2][BATCH][NQ][4];      // fused Rot@RX per layer/sample/wire
__device__ float2 g_CRX[2][NQ];              // (cos(a/2), sin(a/2)) per layer/wire
__device__ float  g_feats[BATCH][NQ];        // PauliZ expvals

__device__ __forceinline__ float2 cmul(float2 a, float2 b) {
    return make_float2(a.x * b.x - a.y * b.y, a.x * b.y + a.y * b.x);
}
__device__ __forceinline__ float2 cadd(float2 a, float2 b) {
    return make_float2(a.x + b.x, a.y + b.y);
}

// ---------------- gate parameter preparation ----------------
// U = Rot(phi,theta,omega) @ RX(x)  (RX applied first in the circuit)
__global__ void k_prep(const float* __restrict__ x,
                       const float* __restrict__ w0, const float* __restrict__ x0,
                       const float* __restrict__ w1, const float* __restrict__ x1) {
    int tid = blockIdx.x * blockDim.x + threadIdx.x;
    if (tid < 2 * BATCH * NQ) {
        int layer = tid >> 10;          // 64*16 = 1024 per layer
        int b = (tid >> 4) & 63;
        int q = tid & 15;
        const float* w = layer ? w1 : w0;

        float hr = 0.5f * x[b * NQ + q];
        float rc = cosf(hr), rs = sinf(hr);
        // RX = [[rc, -i rs], [-i rs, rc]]
        float2 R00 = make_float2(rc, 0.f), R01 = make_float2(0.f, -rs);
        float2 R10 = make_float2(0.f, -rs), R11 = make_float2(rc, 0.f);

        float phi = w[q * 3 + 0], th = 0.5f * w[q * 3 + 1], om = w[q * 3 + 2];
        float ct = cosf(th), st = sinf(th);
        float ap = 0.5f * (phi + om), am = 0.5f * (phi - om);
        float2 A  = make_float2( cosf(ap) * ct, -sinf(ap) * ct);  //  e^{-i ap} ct
        float2 Bm = make_float2(-cosf(am) * st, -sinf(am) * st);  // -e^{+i am} st
        float2 Cm = make_float2( cosf(am) * st, -sinf(am) * st);  //  e^{-i am} st
        float2 Dm = make_float2( cosf(ap) * ct,  sinf(ap) * ct);  //  e^{+i ap} ct

        g_U[layer][b][q][0] = cadd(cmul(A,  R00), cmul(Bm, R10));
        g_U[layer][b][q][1] = cadd(cmul(A,  R01), cmul(Bm, R11));
        g_U[layer][b][q][2] = cadd(cmul(Cm, R00), cmul(Dm, R10));
        g_U[layer][b][q][3] = cadd(cmul(Cm, R01), cmul(Dm, R11));
    }
    if (tid < 2 * NQ) {
        int layer = tid >> 4;
        int q = tid & 15;
        float a = 0.5f * (layer ? x1[q] : x0[q]);
        g_CRX[layer][q] = make_float2(cosf(a), sinf(a));
    }
}

// ---------------- layer-1 single-qubit block: write product state ----------------
// state after all (Rot@RX)|0...0> is a product state: amp(idx) = prod_q U_q[s_q][0]
__global__ void k_init() {
    int b = blockIdx.y;
    int chunk = blockIdx.x;  // 16 chunks of 4096
    int t = threadIdx.x;     // 256 threads
    __shared__ float2 hi[256], lo[256];

    float2 ph = make_float2(1.f, 0.f), pl = make_float2(1.f, 0.f);
#pragma unroll
    for (int q = 0; q < 8; q++) {
        int bit = (t >> (7 - q)) & 1;
        ph = cmul(ph, g_U[0][b][q][bit ? 2 : 0]);       // wires 0..7 (high byte)
        pl = cmul(pl, g_U[0][b][q + 8][bit ? 2 : 0]);   // wires 8..15 (low byte)
    }
    hi[t] = ph; lo[t] = pl;
    __syncthreads();

    size_t sb = ((size_t)b << 16);
    for (int i = t; i < 4096; i += 256) {
        int idx = (chunk << 12) + i;
        g_state[sb + idx] = cmul(hi[idx >> 8], lo[idx & 255]);
    }
}

// ---------------- Pass A: single-qubit U on wires 4..15 (bits 0..11 local) ----------------
__global__ void k_passA(int layer) {
    __shared__ float2 s[4096];
    __shared__ float2 Us[NQ][4];
    int b = blockIdx.y, slab = blockIdx.x;   // 16 slabs of 4096
    int tid = threadIdx.x;                   // 256
    size_t base = ((size_t)b << 16) + ((size_t)slab << 12);

    for (int i = tid; i < 4096; i += 256) s[i] = g_state[base + i];
    if (tid < 64) ((float2*)Us)[tid] = ((const float2*)g_U[layer][b])[tid];
    __syncthreads();

#pragma unroll
    for (int w = 4; w < 16; ++w) {
        int bbit = 15 - w;                   // 11 .. 0
        float2 u00 = Us[w][0], u01 = Us[w][1], u10 = Us[w][2], u11 = Us[w][3];
        for (int p = tid; p < 2048; p += 256) {
            int i0 = ((p >> bbit) << (bbit + 1)) | (p & ((1 << bbit) - 1));
            int i1 = i0 | (1 << bbit);
            float2 a0 = s[i0], a1 = s[i1];
            s[i0] = cadd(cmul(u00, a0), cmul(u01, a1));
            s[i1] = cadd(cmul(u10, a0), cmul(u11, a1));
        }
        __syncthreads();
    }
    for (int i = tid; i < 4096; i += 256) g_state[base + i] = s[i];
}

// ---------------- Pass B: U wires 0..3 (optional) + CRX q=0..4 ----------------
// local bits: l6..l11 <-> g10..g15 ; l0..l5 <-> g0..g5 ; slab = g6..g9 (16 slabs)
__global__ void k_passB(int layer, int applyU) {
    __shared__ float2 s[4096];
    __shared__ float2 Us[4][4];
    __shared__ float2 crx[5];
    int b = blockIdx.y, slab = blockIdx.x;
    int tid = threadIdx.x;
    size_t sb = ((size_t)b << 16);

    for (int i = tid; i < 4096; i += 256) {
        int g = ((i >> 6) << 10) | (slab << 6) | (i & 63);
        s[i] = g_state[sb + g];
    }
    if (tid < 16) ((float2*)Us)[tid] = ((const float2*)g_U[layer][b])[tid];  // wires 0..3
    if (tid < 5)  crx[tid] = g_CRX[layer][tid];
    __syncthreads();

    if (applyU) {
#pragma unroll
        for (int w = 0; w < 4; ++w) {
            int bbit = 11 - w;               // wire0->l11 ... wire3->l8
            float2 u00 = Us[w][0], u01 = Us[w][1], u10 = Us[w][2], u11 = Us[w][3];
            for (int p = tid; p < 2048; p += 256) {
                int i0 = ((p >> bbit) << (bbit + 1)) | (p & ((1 << bbit) - 1));
                int i1 = i0 | (1 << bbit);
                float2 a0 = s[i0], a1 = s[i1];
                s[i0] = cadd(cmul(u00, a0), cmul(u01, a1));
                s[i1] = cadd(cmul(u10, a0), cmul(u11, a1));
            }
            __syncthreads();
        }
    }
#pragma unroll
    for (int k = 0; k < 5; k++) {            // CRX 0..4: (ctrl,tgt)=(11,10)..(7,6)
        int bc = 11 - k, bt = 10 - k;
        float c = crx[k].x, sn = crx[k].y;
        for (int p = tid; p < 2048; p += 256) {
            int i0 = ((p >> bt) << (bt + 1)) | (p & ((1 << bt) - 1));
            if ((i0 >> bc) & 1) {
                int i1 = i0 | (1 << bt);
                float2 a0 = s[i0], a1 = s[i1];
                s[i0] = make_float2(c * a0.x + sn * a1.y, c * a0.y - sn * a1.x);
                s[i1] = make_float2(c * a1.x + sn * a0.y, c * a1.y - sn * a0.x);
            }
        }
        __syncthreads();
    }
    for (int i = tid; i < 4096; i += 256) {
        int g = ((i >> 6) << 10) | (slab << 6) | (i & 63);
        g_state[sb + g] = s[i];
    }
}

// ---------------- Pass C: CRX q=5..15 (incl. ring wrap) ----------------
// local bits: l0..l10 <-> g0..g10 ; l11 <-> g15 ; slab = g11..g14 (16 slabs)
__global__ void k_passC(int layer) {
    __shared__ float2 s[4096];
    __shared__ float2 crx[NQ];
    int b = blockIdx.y, slab = blockIdx.x;
    int tid = threadIdx.x;
    size_t sb = ((size_t)b << 16);

    for (int i = tid; i < 4096; i += 256) {
        int g = ((i >> 11) << 15) | (slab << 11) | (i & 2047);
        s[i] = g_state[sb + g];
    }
    if (tid < 16) crx[tid] = g_CRX[layer][tid];
    __syncthreads();

#pragma unroll
    for (int q = 5; q <= 15; q++) {
        int bc = (q == 15) ? 0  : (15 - q);  // control local bit
        int bt = (q == 15) ? 11 : (14 - q);  // target local bit
        float c = crx[q].x, sn = crx[q].y;
        for (int p = tid; p < 2048; p += 256) {
            int i0 = ((p >> bt) << (bt + 1)) | (p & ((1 << bt) - 1));
            if ((i0 >> bc) & 1) {
                int i1 = i0 | (1 << bt);
                float2 a0 = s[i0], a1 = s[i1];
                s[i0] = make_float2(c * a0.x + sn * a1.y, c * a0.y - sn * a1.x);
                s[i1] = make_float2(c * a1.x + sn * a0.y, c * a1.y - sn * a0.x);
            }
        }
        __syncthreads();
    }
    for (int i = tid; i < 4096; i += 256) {
        int g = ((i >> 11) << 15) | (slab << 11) | (i & 2047);
        g_state[sb + g] = s[i];
    }
}

// ---------------- PauliZ expvals: E_w = sum_idx |amp|^2 * (1-2*bit_w) ----------------
__global__ void k_reduce() {
    int b = blockIdx.x;
    int tid = threadIdx.x;   // 1024 = 32 warps
    float acc[NQ];
#pragma unroll
    for (int w = 0; w < NQ; w++) acc[w] = 0.f;

    size_t sb = ((size_t)b << 16);
    for (int i = tid; i < DIM; i += 1024) {
        float2 a = g_state[sb + i];
        float p = a.x * a.x + a.y * a.y;
#pragma unroll
        for (int w = 0; w < NQ; w++)
            acc[w] += ((i >> (15 - w)) & 1) ? -p : p;
    }
#pragma unroll
    for (int w = 0; w < NQ; w++)
#pragma unroll
        for (int off = 16; off; off >>= 1)
            acc[w] += __shfl_xor_sync(0xffffffffu, acc[w], off);

    __shared__ float sh[32][NQ];
    int warp = tid >> 5, lane = tid & 31;
    if (lane == 0) {
#pragma unroll
        for (int w = 0; w < NQ; w++) sh[warp][w] = acc[w];
    }
    __syncthreads();
    if (tid < NQ) {
        float sum = 0.f;
#pragma unroll
        for (int k = 0; k < 32; k++) sum += sh[k][tid];
        g_feats[b][tid] = sum;
    }
}

// ---------------- linear head + log_softmax ----------------
__global__ void k_head(const float* __restrict__ fc_w, const float* __restrict__ fc_b,
                       float* __restrict__ out) {
    int b = threadIdx.x;
    if (b < BATCH) {
        float f[NQ];
#pragma unroll
        for (int w = 0; w < NQ; w++) f[w] = g_feats[b][w];
        float lg[NCLS];
        float m = -1e30f;
#pragma unroll
        for (int c = 0; c < NCLS; c++) {
            float v = fc_b[c];
#pragma unroll
            for (int w = 0; w < NQ; w++) v += fc_w[c * NQ + w] * f[w];
            lg[c] = v;
            m = fmaxf(m, v);
        }
        float sum = 0.f;
#pragma unroll
        for (int c = 0; c < NCLS; c++) sum += expf(lg[c] - m);
        float lse = m + logf(sum);
#pragma unroll
        for (int c = 0; c < NCLS; c++) out[b * NCLS + c] = lg[c] - lse;
    }
}

// ---------------- launcher ----------------
extern "C" void kernel_launch(void* const* d_in, const int* in_sizes, int n_in,
                              void* d_out, int out_size) {
    const float* x    = (const float*)d_in[0];
    const float* w0   = (const float*)d_in[1];
    const float* x0   = (const float*)d_in[2];
    const float* w1   = (const float*)d_in[3];
    const float* x1   = (const float*)d_in[4];
    const float* fc_w = (const float*)d_in[5];
    const float* fc_b = (const float*)d_in[6];
    float* out = (float*)d_out;

    k_prep<<<2, 1024>>>(x, w0, x0, w1, x1);
    k_init<<<dim3(16, BATCH), 256>>>();          // layer 1 single-qubit block (product state)
    k_passB<<<dim3(16, BATCH), 256>>>(0, 0);     // layer 1: CRX 0..4
    k_passC<<<dim3(16, BATCH), 256>>>(0);        // layer 1: CRX 5..15
    k_passA<<<dim3(16, BATCH), 256>>>(1);        // layer 2: U wires 4..15
    k_passB<<<dim3(16, BATCH), 256>>>(1, 1);     // layer 2: U wires 0..3 + CRX 0..4
    k_passC<<<dim3(16, BATCH), 256>>>(1);        // layer 2: CRX 5..15
    k_reduce<<<BATCH, 1024>>>();
    k_head<<<1, 64>>>(fc_w, fc_b, out);
}

// round 2
// speedup vs baseline: 2.0939x; 2.0939x over previous
#include <cuda_runtime.h>
#include <math.h>

#define NQ    16
#define DIM   65536
#define BATCH 64
#define NCLS  23

// ---------------- scratch ----------------
__device__ float2 g_state[BATCH * DIM];      // 32 MB state (L2-resident)
__device__ float2 g_U[2][BATCH][NQ][4];      // fused Rot@RX per layer/sample/wire
__device__ float2 g_CRX[2][NQ];              // (cos(a/2), sin(a/2)) per layer/wire
__device__ float  g_part[BATCH][16][NQ];     // per-slab partial expvals

__device__ __forceinline__ float2 cmul(float2 a, float2 b) {
    return make_float2(a.x * b.x - a.y * b.y, a.x * b.y + a.y * b.x);
}
__device__ __forceinline__ float2 cadd(float2 a, float2 b) {
    return make_float2(a.x + b.x, a.y + b.y);
}
// shared-memory skew to avoid bank conflicts across all remap patterns
__device__ __forceinline__ int SK(int a) { return a + (a >> 4); }

// ---------------- register gates (window of 4 bits -> 16 amps/thread) ----------------
template<int RB>
__device__ __forceinline__ void uG(float2* v, const float2* __restrict__ U) {
    float2 u00 = U[0], u01 = U[1], u10 = U[2], u11 = U[3];
#pragma unroll
    for (int i = 0; i < 16; i++) {
        if (!(i & (1 << RB))) {
            float2 a0 = v[i], a1 = v[i | (1 << RB)];
            v[i]            = cadd(cmul(u00, a0), cmul(u01, a1));
            v[i | (1 << RB)] = cadd(cmul(u10, a0), cmul(u11, a1));
        }
    }
}
template<int CB, int TB>
__device__ __forceinline__ void crxG(float2* v, float2 cs) {
    float c = cs.x, sn = cs.y;
#pragma unroll
    for (int i = 0; i < 16; i++) {
        if ((i & (1 << CB)) && !(i & (1 << TB))) {
            float2 a0 = v[i], a1 = v[i | (1 << TB)];
            v[i]            = make_float2(c * a0.x + sn * a1.y, c * a0.y - sn * a1.x);
            v[i | (1 << TB)] = make_float2(c * a1.x + sn * a0.y, c * a1.y - sn * a0.x);
        }
    }
}

// ---------------- gate parameter preparation ----------------
__global__ void k_prep(const float* __restrict__ x,
                       const float* __restrict__ w0, const float* __restrict__ x0,
                       const float* __restrict__ w1, const float* __restrict__ x1) {
    int tid = blockIdx.x * blockDim.x + threadIdx.x;
    if (tid < 2 * BATCH * NQ) {
        int layer = tid >> 10;
        int b = (tid >> 4) & 63;
        int q = tid & 15;
        const float* w = layer ? w1 : w0;

        float hr = 0.5f * x[b * NQ + q];
        float rc = cosf(hr), rs = sinf(hr);
        float2 R00 = make_float2(rc, 0.f), R01 = make_float2(0.f, -rs);
        float2 R10 = make_float2(0.f, -rs), R11 = make_float2(rc, 0.f);

        float phi = w[q * 3 + 0], th = 0.5f * w[q * 3 + 1], om = w[q * 3 + 2];
        float ct = cosf(th), st = sinf(th);
        float ap = 0.5f * (phi + om), am = 0.5f * (phi - om);
        float2 A  = make_float2( cosf(ap) * ct, -sinf(ap) * ct);
        float2 Bm = make_float2(-cosf(am) * st, -sinf(am) * st);
        float2 Cm = make_float2( cosf(am) * st, -sinf(am) * st);
        float2 Dm = make_float2( cosf(ap) * ct,  sinf(ap) * ct);

        g_U[layer][b][q][0] = cadd(cmul(A,  R00), cmul(Bm, R10));
        g_U[layer][b][q][1] = cadd(cmul(A,  R01), cmul(Bm, R11));
        g_U[layer][b][q][2] = cadd(cmul(Cm, R00), cmul(Dm, R10));
        g_U[layer][b][q][3] = cadd(cmul(Cm, R01), cmul(Dm, R11));
    }
    if (tid < 2 * NQ) {
        int layer = tid >> 4;
        int q = tid & 15;
        float a = 0.5f * (layer ? x1[q] : x0[q]);
        g_CRX[layer][q] = make_float2(cosf(a), sinf(a));
    }
}

// =====================================================================
// B mapping: L11..L6 <-> g15..g10, L5..L0 <-> g5..g0, slab = g9..g6
//   W1: L = r<<8 | w<<5 | l   (regs L11..8, warps L7..5, lanes L4..0)
//   W2: L = w<<9 | r<<5 | l   (warps L11..9, regs L8..5, lanes L4..0)
// =====================================================================
__device__ __forceinline__ int bmap_g(int L, int slab) {
    return ((L >> 6) << 10) | (slab << 6) | (L & 63);
}

// k_B0: product state (layer-1 single-qubit block on |0..0>) + CRX_L1 q=0..4
__global__ void __launch_bounds__(256) k_B0() {
    __shared__ float2 s[4352];
    int b = blockIdx.y, slab = blockIdx.x;
    int tid = threadIdx.x, w = tid >> 5, l = tid & 31;
    size_t sb = ((size_t)b << 16);
    float2 v[16];
    const float2* U0 = (const float2*)g_U[0][b];
    const float2* CX = (const float2*)g_CRX[0];

    // thread-fixed wires: 4<-w2, 5<-w1, 10<-w0, 11..15<-l4..l0, 6..9<-slab3..0
    float2 C = U0[4 * 4 + (((w >> 2) & 1) ? 2 : 0)];
    C = cmul(C, U0[5 * 4 + (((w >> 1) & 1) ? 2 : 0)]);
    C = cmul(C, U0[10 * 4 + ((w & 1) ? 2 : 0)]);
    C = cmul(C, U0[11 * 4 + (((l >> 4) & 1) ? 2 : 0)]);
    C = cmul(C, U0[12 * 4 + (((l >> 3) & 1) ? 2 : 0)]);
    C = cmul(C, U0[13 * 4 + (((l >> 2) & 1) ? 2 : 0)]);
    C = cmul(C, U0[14 * 4 + (((l >> 1) & 1) ? 2 : 0)]);
    C = cmul(C, U0[15 * 4 + ((l & 1) ? 2 : 0)]);
    C = cmul(C, U0[6 * 4 + (((slab >> 3) & 1) ? 2 : 0)]);
    C = cmul(C, U0[7 * 4 + (((slab >> 2) & 1) ? 2 : 0)]);
    C = cmul(C, U0[8 * 4 + (((slab >> 1) & 1) ? 2 : 0)]);
    C = cmul(C, U0[9 * 4 + ((slab & 1) ? 2 : 0)]);
#pragma unroll
    for (int r = 0; r < 16; r++) {  // wires 0..3 <-> r3..r0
        float2 t = cmul(U0[0 * 4 + (((r >> 3) & 1) ? 2 : 0)], U0[1 * 4 + (((r >> 2) & 1) ? 2 : 0)]);
        t = cmul(t, U0[2 * 4 + (((r >> 1) & 1) ? 2 : 0)]);
        t = cmul(t, U0[3 * 4 + ((r & 1) ? 2 : 0)]);
        v[r] = cmul(C, t);
    }
    // W1 regs = g15..g12 = wires 0..3 : CRX q0 (0,1)=(rb3,rb2), q1=(rb2,rb1), q2=(rb1,rb0)
    crxG<3, 2>(v, CX[0]);
    crxG<2, 1>(v, CX[1]);
    crxG<1, 0>(v, CX[2]);
    // remap W1 -> W2
#pragma unroll
    for (int r = 0; r < 16; r++) s[SK((r << 8) | (w << 5) | l)] = v[r];
    __syncthreads();
#pragma unroll
    for (int r = 0; r < 16; r++) v[r] = s[SK((w << 9) | (r << 5) | l)];
    // W2 regs = L8..L5 = g12,g11,g10,g5 = wires 3,4,5,10 : CRX q3 (3,4)=(rb3,rb2), q4 (4,5)=(rb2,rb1)
    crxG<3, 2>(v, CX[3]);
    crxG<2, 1>(v, CX[4]);
    // store (coalesced)
#pragma unroll
    for (int r = 0; r < 16; r++) {
        int L = (w << 9) | (r << 5) | l;
        g_state[sb + bmap_g(L, slab)] = v[r];
    }
}

// k_B1: U_L2 wires 1..4 + CRX_L2 q=0..4
__global__ void __launch_bounds__(256) k_B1() {
    __shared__ float2 s[4352];
    int b = blockIdx.y, slab = blockIdx.x;
    int tid = threadIdx.x, w = tid >> 5, l = tid & 31;
    size_t sb = ((size_t)b << 16);
    float2 v[16];
    const float2* U1 = (const float2*)g_U[1][b];
    const float2* CX = (const float2*)g_CRX[1];

#pragma unroll
    for (int r = 0; r < 16; r++) {
        int L = (r << 8) | (w << 5) | l;
        v[r] = g_state[sb + bmap_g(L, slab)];
    }
    // W1 regs = wires 0..3 (rb3..rb0): U wires 1,2,3 then CRX q0,q1,q2
    uG<2>(v, U1 + 1 * 4);
    uG<1>(v, U1 + 2 * 4);
    uG<0>(v, U1 + 3 * 4);
    crxG<3, 2>(v, CX[0]);
    crxG<2, 1>(v, CX[1]);
    crxG<1, 0>(v, CX[2]);
    // remap
#pragma unroll
    for (int r = 0; r < 16; r++) s[SK((r << 8) | (w << 5) | l)] = v[r];
    __syncthreads();
#pragma unroll
    for (int r = 0; r < 16; r++) v[r] = s[SK((w << 9) | (r << 5) | l)];
    // W2 regs = wires 3,4,5,10: U wire4 (rb2), CRX q3 (rb3,rb2), q4 (rb2,rb1)
    uG<2>(v, U1 + 4 * 4);
    crxG<3, 2>(v, CX[3]);
    crxG<2, 1>(v, CX[4]);
#pragma unroll
    for (int r = 0; r < 16; r++) {
        int L = (w << 9) | (r << 5) | l;
        g_state[sb + bmap_g(L, slab)] = v[r];
    }
}

// =====================================================================
// C mapping: L10..L0 <-> g10..g0, L11 <-> g15, slab = g14..g11
// Windows:
//   W1: regs L10..7, warps {L11,L6,L5}, lanes L4..0
//   W2: regs L7..4,  warps L11..9, lanes {L8,L3..0}
//   W3: regs L4..1,  warps L11..9, lanes {L8..5,L0}
//   W4: regs {L11,L10,L1,L0}, warps L9..7, lanes L6..2
// =====================================================================
__device__ __forceinline__ int cmap_g(int L, int slab) {
    return ((L >> 11) << 15) | (slab << 11) | (L & 2047);
}

template<int CL, bool DOU, bool RED>
__global__ void __launch_bounds__(256) k_C() {
    __shared__ float2 s[4352];
    int b = blockIdx.y, slab = blockIdx.x;
    int tid = threadIdx.x, w = tid >> 5, l = tid & 31;
    size_t sb = ((size_t)b << 16);
    float2 v[16];
    const float2* U1 = (const float2*)g_U[1][b];
    const float2* CX = (const float2*)g_CRX[CL];

    // W1 load (coalesced)
    int A1b = ((w & 4) << 9) | ((w & 3) << 5) | l;
#pragma unroll
    for (int r = 0; r < 16; r++) v[r] = g_state[sb + cmap_g(A1b | (r << 7), slab)];
    // W1 regs = L10,9,8,7 = wires 5,6,7,8: CRX q5,q6,q7 then U wires 5,6,7
    crxG<3, 2>(v, CX[5]);
    crxG<2, 1>(v, CX[6]);
    crxG<1, 0>(v, CX[7]);
    if (DOU) { uG<3>(v, U1 + 5 * 4); uG<2>(v, U1 + 6 * 4); uG<1>(v, U1 + 7 * 4); }
    // remap W1 -> W2
#pragma unroll
    for (int r = 0; r < 16; r++) s[SK(A1b | (r << 7))] = v[r];
    __syncthreads();
    int A2b = (w << 9) | ((l & 16) << 4) | (l & 15);
#pragma unroll
    for (int r = 0; r < 16; r++) v[r] = s[SK(A2b | (r << 4))];
    __syncthreads();
    // W2 regs = L7..L4 = wires 8..11: CRX q8,q9,q10 then U wires 8,9,10
    crxG<3, 2>(v, CX[8]);
    crxG<2, 1>(v, CX[9]);
    crxG<1, 0>(v, CX[10]);
    if (DOU) { uG<3>(v, U1 + 8 * 4); uG<2>(v, U1 + 9 * 4); uG<1>(v, U1 + 10 * 4); }
    // remap W2 -> W3
#pragma unroll
    for (int r = 0; r < 16; r++) s[SK(A2b | (r << 4))] = v[r];
    __syncthreads();
    int A3b = (w << 9) | ((l >> 1) << 5) | (l & 1);
#pragma unroll
    for (int r = 0; r < 16; r++) v[r] = s[SK(A3b | (r << 1))];
    __syncthreads();
    // W3 regs = L4..L1 = wires 11..14: CRX q11,q12,q13 then U wires 11,12,13
    crxG<3, 2>(v, CX[11]);
    crxG<2, 1>(v, CX[12]);
    crxG<1, 0>(v, CX[13]);
    if (DOU) { uG<3>(v, U1 + 11 * 4); uG<2>(v, U1 + 12 * 4); uG<1>(v, U1 + 13 * 4); }
    // remap W3 -> W4
#pragma unroll
    for (int r = 0; r < 16; r++) s[SK(A3b | (r << 1))] = v[r];
    __syncthreads();
    int A4b = (w << 7) | (l << 2);
#pragma unroll
    for (int r = 0; r < 16; r++) v[r] = s[SK(A4b | ((r & 12) << 8) | (r & 3))];
    __syncthreads();
    // W4 regs: rb3->L11(wire0), rb2->L10(wire5), rb1->L1(wire14), rb0->L0(wire15)
    crxG<1, 0>(v, CX[14]);
    crxG<0, 3>(v, CX[15]);
    if (DOU) { uG<1>(v, U1 + 14 * 4); uG<0>(v, U1 + 15 * 4); uG<3>(v, U1 + 0 * 4); }

    if (!RED) {
        // stage through shared for coalesced store
#pragma unroll
        for (int r = 0; r < 16; r++) s[SK(A4b | ((r & 12) << 8) | (r & 3))] = v[r];
        __syncthreads();
        for (int i = tid; i < 4096; i += 256)
            g_state[sb + cmap_g(i, slab)] = s[SK(i)];
    } else {
        // PauliZ reduction directly from registers.
        // reg bits -> wires: rb3->0, rb2->5, rb1->14, rb0->15
        float sall = 0.f, e0 = 0.f, e5 = 0.f, e14 = 0.f, e15 = 0.f;
#pragma unroll
        for (int r = 0; r < 16; r++) {
            float p = v[r].x * v[r].x + v[r].y * v[r].y;
            sall += p;
            e0  += (r & 8) ? -p : p;
            e5  += (r & 4) ? -p : p;
            e14 += (r & 2) ? -p : p;
            e15 += (r & 1) ? -p : p;
        }
        float e[NQ];
        e[0] = e0; e[5] = e5; e[14] = e14; e[15] = e15;
        // warps (L9..7 = g9..7) -> wires 6,7,8 ; lanes (L6..2 = g6..2) -> wires 9..13
        e[6] = (w & 4) ? -sall : sall;
        e[7] = (w & 2) ? -sall : sall;
        e[8] = (w & 1) ? -sall : sall;
        e[9]  = (l & 16) ? -sall : sall;
        e[10] = (l & 8)  ? -sall : sall;
        e[11] = (l & 4)  ? -sall : sall;
        e[12] = (l & 2)  ? -sall : sall;
        e[13] = (l & 1)  ? -sall : sall;
        // slab (g14..11) -> wires 1..4
        e[1] = (slab & 8) ? -sall : sall;
        e[2] = (slab & 4) ? -sall : sall;
        e[3] = (slab & 2) ? -sall : sall;
        e[4] = (slab & 1) ? -sall : sall;
#pragma unroll
        for (int k = 0; k < NQ; k++)
#pragma unroll
            for (int off = 16; off; off >>= 1)
                e[k] += __shfl_xor_sync(0xffffffffu, e[k], off);
        float* sf = (float*)s;
        int lane = tid & 31;
        if (lane == 0) {
#pragma unroll
            for (int k = 0; k < NQ; k++) sf[w * NQ + k] = e[k];
        }
        __syncthreads();
        if (tid < NQ) {
            float sum = 0.f;
#pragma unroll
            for (int k = 0; k < 8; k++) sum += sf[k * NQ + tid];
            g_part[b][slab][tid] = sum;
        }
    }
}

// ---------------- linear head + log_softmax ----------------
__global__ void k_head(const float* __restrict__ fc_w, const float* __restrict__ fc_b,
                       float* __restrict__ out) {
    int b = threadIdx.x;
    if (b < BATCH) {
        float f[NQ];
#pragma unroll
        for (int w = 0; w < NQ; w++) {
            float sum = 0.f;
#pragma unroll
            for (int sl = 0; sl < 16; sl++) sum += g_part[b][sl][w];
            f[w] = sum;
        }
        float lg[NCLS];
        float m = -1e30f;
#pragma unroll
        for (int c = 0; c < NCLS; c++) {
            float v = fc_b[c];
#pragma unroll
            for (int w = 0; w < NQ; w++) v += fc_w[c * NQ + w] * f[w];
            lg[c] = v;
            m = fmaxf(m, v);
        }
        float sum = 0.f;
#pragma unroll
        for (int c = 0; c < NCLS; c++) sum += expf(lg[c] - m);
        float lse = m + logf(sum);
#pragma unroll
        for (int c = 0; c < NCLS; c++) out[b * NCLS + c] = lg[c] - lse;
    }
}

// ---------------- launcher ----------------
extern "C" void kernel_launch(void* const* d_in, const int* in_sizes, int n_in,
                              void* d_out, int out_size) {
    const float* x    = (const float*)d_in[0];
    const float* w0   = (const float*)d_in[1];
    const float* x0   = (const float*)d_in[2];
    const float* w1   = (const float*)d_in[3];
    const float* x1   = (const float*)d_in[4];
    const float* fc_w = (const float*)d_in[5];
    const float* fc_b = (const float*)d_in[6];
    float* out = (float*)d_out;

    k_prep<<<2, 1024>>>(x, w0, x0, w1, x1);
    k_B0<<<dim3(16, BATCH), 256>>>();                 // init product state + CRX_L1 0..4
    k_C<0, true, false><<<dim3(16, BATCH), 256>>>();  // CRX_L1 5..15 + U_L2 wires {0,5..15}
    k_B1<<<dim3(16, BATCH), 256>>>();                 // U_L2 wires 1..4 + CRX_L2 0..4
    k_C<1, false, true><<<dim3(16, BATCH), 256>>>();  // CRX_L2 5..15 + PauliZ reduce
    k_head<<<1, 64>>>(fc_w, fc_b, out);
}